// round 1
// baseline (speedup 1.0000x reference)
#include <cuda_runtime.h>
#include <cuda_bf16.h>

#define N_  64
#define T_  2048
#define D_  256
#define V_  256
#define CHUNK 128
#define SPLITS (T_ / CHUNK)   // 16

// Scratch (no allocation allowed in kernel_launch)
__device__ float g_m[N_ * SPLITS];            // per-chunk max
__device__ float g_l[N_ * SPLITS];            // per-chunk sum of exp
__device__ float g_ctx[N_ * SPLITS * V_];     // per-chunk unnormalized context
__device__ float g_s[N_ * SPLITS];            // final per-chunk attention scale

// ---------------------------------------------------------------------------
// Kernel 1: per (row, T-chunk) partial attention.
//   - skips all key/value traffic for fully-masked chunks (t >= lens[n])
//   - writes p = exp(e - m_chunk) into the attention output region
//   - writes (m, l, ctx_partial) to scratch
// ---------------------------------------------------------------------------
__global__ void __launch_bounds__(256)
attn_partial(const float* __restrict__ q,
             const float* __restrict__ key,
             const float* __restrict__ value,
             const int*   __restrict__ lens,
             float*       __restrict__ att_out)
{
    const int n   = blockIdx.y;
    const int c   = blockIdx.x;
    const int tid = threadIdx.x;
    const int t0  = c * CHUNK;
    const int base = n * SPLITS + c;

    float* att = att_out + (size_t)n * T_ + t0;

    __shared__ float sq[D_];
    __shared__ float sp[CHUNK];
    __shared__ float sred[8];
    __shared__ float4 sacc[4][V_ / 4];

    int valid = lens[n] - t0;
    if (valid > CHUNK) valid = CHUNK;

    if (valid <= 0) {
        // Fully masked chunk: attention is exactly 0, no key/value reads.
        if (tid < CHUNK) att[tid] = 0.0f;
        g_ctx[(size_t)base * V_ + tid] = 0.0f;
        if (tid == 0) { g_m[base] = -1e30f; g_l[base] = 0.0f; }
        return;
    }

    sq[tid] = q[n * D_ + tid];
    __syncthreads();

    // ---- energy: one warp per t, coalesced float4 key loads ----
    const int w    = tid >> 5;
    const int lane = tid & 31;
    const float* kbase = key + ((size_t)n * T_ + t0) * D_;

    for (int t = w; t < CHUNK; t += 8) {
        float e = -1e30f;
        if (t < valid) {
            const float4* kr = (const float4*)(kbase + (size_t)t * D_);
            float acc = 0.0f;
            #pragma unroll
            for (int i = 0; i < 2; i++) {
                float4 kv = kr[lane + 32 * i];
                int d = (lane + 32 * i) * 4;
                acc += kv.x * sq[d] + kv.y * sq[d + 1] + kv.z * sq[d + 2] + kv.w * sq[d + 3];
            }
            #pragma unroll
            for (int o = 16; o > 0; o >>= 1)
                acc += __shfl_xor_sync(0xffffffffu, acc, o);
            e = acc;
        }
        if (lane == 0) sp[t] = e;
    }
    __syncthreads();

    // ---- block max over sp[0..CHUNK) ----
    float mv = (tid < CHUNK) ? sp[tid] : -1e30f;
    #pragma unroll
    for (int o = 16; o > 0; o >>= 1)
        mv = fmaxf(mv, __shfl_xor_sync(0xffffffffu, mv, o));
    if (lane == 0) sred[w] = mv;
    __syncthreads();
    if (tid < 8) {
        float x = sred[tid];
        #pragma unroll
        for (int o = 4; o > 0; o >>= 1)
            x = fmaxf(x, __shfl_xor_sync(0xffu, x, o, 8));
        if (tid == 0) sred[0] = x;
    }
    __syncthreads();
    const float m = sred[0];

    // ---- p = exp(e - m), write to output, block sum -> l ----
    float p = (tid < valid) ? __expf(sp[tid] - m) : 0.0f;
    if (tid < CHUNK) att[tid] = p;

    float ps = p;
    #pragma unroll
    for (int o = 16; o > 0; o >>= 1)
        ps += __shfl_xor_sync(0xffffffffu, ps, o);
    __syncthreads();                  // sred reuse
    if (lane == 0) sred[w] = ps;
    if (tid < CHUNK) sp[tid] = p;     // overwrite energies with weights
    __syncthreads();
    if (tid == 0) {
        float l = 0.0f;
        #pragma unroll
        for (int i = 0; i < 8; i++) l += sred[i];
        g_l[base] = l;
        g_m[base] = m;
    }

    // ---- ctx_partial[v] = sum_t p[t] * value[n, t0+t, v], float4 loads ----
    const int vq = tid & 63;          // which float4 of V
    const int ts = tid >> 6;          // t-subgroup 0..3
    const float4* vb = (const float4*)(value + ((size_t)n * T_ + t0) * V_) + vq;

    float4 acc = make_float4(0.f, 0.f, 0.f, 0.f);
    #pragma unroll 4
    for (int t = ts; t < valid; t += 4) {
        float  pw = sp[t];
        float4 vv = vb[(size_t)t * (V_ / 4)];
        acc.x += pw * vv.x;
        acc.y += pw * vv.y;
        acc.z += pw * vv.z;
        acc.w += pw * vv.w;
    }
    sacc[ts][vq] = acc;
    __syncthreads();
    if (ts == 0) {
        float4 a0 = sacc[0][vq], a1 = sacc[1][vq], a2 = sacc[2][vq], a3 = sacc[3][vq];
        float4 r;
        r.x = a0.x + a1.x + a2.x + a3.x;
        r.y = a0.y + a1.y + a2.y + a3.y;
        r.z = a0.z + a1.z + a2.z + a3.z;
        r.w = a0.w + a1.w + a2.w + a3.w;
        ((float4*)(g_ctx + (size_t)base * V_))[vq] = r;
    }
}

// ---------------------------------------------------------------------------
// Kernel 2: combine partials per row -> context, and per-chunk scales
// ---------------------------------------------------------------------------
__global__ void __launch_bounds__(256)
attn_combine(float* __restrict__ ctx_out)
{
    const int n   = blockIdx.x;
    const int tid = threadIdx.x;

    float M = -1e30f;
    #pragma unroll
    for (int c = 0; c < SPLITS; c++) M = fmaxf(M, g_m[n * SPLITS + c]);

    float L = 0.0f;
    float s[SPLITS];
    #pragma unroll
    for (int c = 0; c < SPLITS; c++) {
        s[c] = __expf(g_m[n * SPLITS + c] - M);   // 0 for empty chunks
        L += g_l[n * SPLITS + c] * s[c];
    }
    const float inv = 1.0f / L;

    if (tid < SPLITS) g_s[n * SPLITS + tid] = s[tid] * inv;

    float acc = 0.0f;
    #pragma unroll
    for (int c = 0; c < SPLITS; c++)
        acc += g_ctx[(size_t)(n * SPLITS + c) * V_ + tid] * s[c];
    ctx_out[n * V_ + tid] = acc * inv;
}

// ---------------------------------------------------------------------------
// Kernel 3: rescale attention in place: att[n,t] *= g_s[n, t/CHUNK]
// ---------------------------------------------------------------------------
__global__ void __launch_bounds__(256)
attn_scale(float* __restrict__ att)
{
    const int i = blockIdx.x * blockDim.x + threadIdx.x;   // over N*T/4 float4s
    const int n = i >> 9;                                  // / (T_/4 = 512)
    const int c = (i & 511) >> 5;                          // / (CHUNK/4 = 32)
    const float sc = g_s[n * SPLITS + c];
    float4* a4 = (float4*)att;
    float4 v = a4[i];
    v.x *= sc; v.y *= sc; v.z *= sc; v.w *= sc;
    a4[i] = v;
}

extern "C" void kernel_launch(void* const* d_in, const int* in_sizes, int n_in,
                              void* d_out, int out_size)
{
    const float* q     = (const float*)d_in[0];
    const float* key   = (const float*)d_in[1];
    const float* value = (const float*)d_in[2];
    const int*   lens  = (const int*)  d_in[3];

    float* out = (float*)d_out;
    float* ctx = out;                 // (N, V)
    float* att = out + N_ * V_;       // (N, T)

    dim3 gA(SPLITS, N_);
    attn_partial<<<gA, 256>>>(q, key, value, lens, att);
    attn_combine<<<N_, 256>>>(ctx);
    attn_scale<<<(N_ * T_ / 4) / 256, 256>>>(att);
}

// round 2
// speedup vs baseline: 1.1323x; 1.1323x over previous
#include <cuda_runtime.h>
#include <cuda_bf16.h>

#define N_  64
#define T_  2048
#define D_  256
#define V_  256
#define CHUNK 128
#define SPLITS (T_ / CHUNK)   // 16

// Scratch (no allocation allowed in kernel_launch)
__device__ float g_m[N_ * SPLITS];            // per-chunk max
__device__ float g_l[N_ * SPLITS];            // per-chunk sum of exp
__device__ float g_ctx[N_ * SPLITS * V_];     // per-chunk unnormalized context

// ---------------------------------------------------------------------------
// Kernel 1: per (row, T-chunk) partial attention.
//   - no key/value traffic for fully-masked chunks
//   - energy phase: 16 independent per-t partials per lane (MLP ~32)
//   - writes p = exp(e - m_chunk) into the attention output region
// ---------------------------------------------------------------------------
__global__ void __launch_bounds__(256, 4)
attn_partial(const float* __restrict__ q,
             const float* __restrict__ key,
             const float* __restrict__ value,
             const int*   __restrict__ lens,
             float*       __restrict__ att_out)
{
    const int n   = blockIdx.y;
    const int c   = blockIdx.x;
    const int tid = threadIdx.x;
    const int t0  = c * CHUNK;
    const int base = n * SPLITS + c;

    float* att = att_out + (size_t)n * T_ + t0;

    __shared__ float sq[D_];
    __shared__ float sp[CHUNK];
    __shared__ float sred[8];
    __shared__ float4 sacc[4][V_ / 4];

    int valid = lens[n] - t0;
    if (valid > CHUNK) valid = CHUNK;

    if (valid <= 0) {
        // Fully masked chunk: attention exactly 0; combine multiplies our
        // g_ctx slot by exactly 0, so no need to zero it.
        if (tid < CHUNK) att[tid] = 0.0f;
        if (tid == 0) { g_m[base] = -1e30f; g_l[base] = 0.0f; }
        return;
    }

    sq[tid] = q[n * D_ + tid];
    __syncthreads();

    const int w    = tid >> 5;
    const int lane = tid & 31;
    const float4* kr = (const float4*)(key + ((size_t)n * T_ + t0) * D_);
    const float4 qA = ((const float4*)sq)[lane];
    const float4 qB = ((const float4*)sq)[lane + 32];

    // ---- energy: warp w owns t = w + 8k, k=0..15; all loads independent ----
    float acc[16];
    #pragma unroll
    for (int k = 0; k < 16; k++) {
        const int t = w + 8 * k;
        acc[k] = 0.0f;
        if (t < valid) {
            const float4* row = kr + (size_t)t * (D_ / 4);
            float4 a = row[lane];
            float4 b = row[lane + 32];
            acc[k] = a.x * qA.x + a.y * qA.y + a.z * qA.z + a.w * qA.w
                   + b.x * qB.x + b.y * qB.y + b.z * qB.z + b.w * qB.w;
        }
    }
    // 16 independent shuffle-reduction chains (pipelined)
    #pragma unroll
    for (int k = 0; k < 16; k++) {
        float e = acc[k];
        #pragma unroll
        for (int o = 16; o > 0; o >>= 1)
            e += __shfl_xor_sync(0xffffffffu, e, o);
        const int t = w + 8 * k;
        if (lane == 0) sp[t] = (t < valid) ? e : -1e30f;
    }
    __syncthreads();

    // ---- block max over sp[0..CHUNK) ----
    float mv = (tid < CHUNK) ? sp[tid] : -1e30f;
    #pragma unroll
    for (int o = 16; o > 0; o >>= 1)
        mv = fmaxf(mv, __shfl_xor_sync(0xffffffffu, mv, o));
    if (lane == 0) sred[w] = mv;
    __syncthreads();
    if (tid < 8) {
        float x = sred[tid];
        #pragma unroll
        for (int o = 4; o > 0; o >>= 1)
            x = fmaxf(x, __shfl_xor_sync(0xffu, x, o, 8));
        if (tid == 0) sred[0] = x;
    }
    __syncthreads();
    const float m = sred[0];

    // ---- p = exp(e - m), write to output, block sum -> l ----
    float p = (tid < valid) ? __expf(sp[tid] - m) : 0.0f;
    if (tid < CHUNK) att[tid] = p;

    float ps = p;
    #pragma unroll
    for (int o = 16; o > 0; o >>= 1)
        ps += __shfl_xor_sync(0xffffffffu, ps, o);
    __syncthreads();                  // sred/sp reuse
    if (lane == 0) sred[w] = ps;
    if (tid < CHUNK) sp[tid] = p;     // overwrite energies with weights
    __syncthreads();
    if (tid == 0) {
        float l = 0.0f;
        #pragma unroll
        for (int i = 0; i < 8; i++) l += sred[i];
        g_l[base] = l;
        g_m[base] = m;
    }

    // ---- ctx_partial[v] = sum_t p[t] * value[n, t0+t, v] ----
    const int vq = tid & 63;          // which float4 of V
    const int ts = tid >> 6;          // t-subgroup 0..3
    const float4* vb = (const float4*)(value + ((size_t)n * T_ + t0) * V_) + vq;

    float4 acc4 = make_float4(0.f, 0.f, 0.f, 0.f);
    #pragma unroll 8
    for (int t = ts; t < valid; t += 4) {
        float  pw = sp[t];
        float4 vv = vb[(size_t)t * (V_ / 4)];
        acc4.x += pw * vv.x;
        acc4.y += pw * vv.y;
        acc4.z += pw * vv.z;
        acc4.w += pw * vv.w;
    }
    sacc[ts][vq] = acc4;
    __syncthreads();
    if (ts == 0) {
        float4 a0 = sacc[0][vq], a1 = sacc[1][vq], a2 = sacc[2][vq], a3 = sacc[3][vq];
        float4 r;
        r.x = a0.x + a1.x + a2.x + a3.x;
        r.y = a0.y + a1.y + a2.y + a3.y;
        r.z = a0.z + a1.z + a2.z + a3.z;
        r.w = a0.w + a1.w + a2.w + a3.w;
        ((float4*)(g_ctx + (size_t)base * V_))[vq] = r;
    }
}

// ---------------------------------------------------------------------------
// Kernel 2: combine partials per row -> context, and rescale attention
//           in place for t < lens[n] (masked region is already 0)
// ---------------------------------------------------------------------------
__global__ void __launch_bounds__(256)
attn_combine(float* __restrict__ ctx_out,
             float* __restrict__ att,
             const int* __restrict__ lens)
{
    const int n   = blockIdx.x;
    const int tid = threadIdx.x;

    float M = -1e30f;
    #pragma unroll
    for (int c = 0; c < SPLITS; c++) M = fmaxf(M, g_m[n * SPLITS + c]);

    float L = 0.0f;
    float s[SPLITS];
    #pragma unroll
    for (int c = 0; c < SPLITS; c++) {
        s[c] = __expf(g_m[n * SPLITS + c] - M);   // exactly 0 for empty chunks
        L += g_l[n * SPLITS + c] * s[c];
    }
    const float inv = 1.0f / L;
    #pragma unroll
    for (int c = 0; c < SPLITS; c++) s[c] *= inv;

    float acc = 0.0f;
    #pragma unroll
    for (int c = 0; c < SPLITS; c++)
        acc += g_ctx[(size_t)(n * SPLITS + c) * V_ + tid] * s[c];
    ctx_out[n * V_ + tid] = acc;

    // rescale attention for this row: only t < lens[n] is nonzero
    float4* a4 = (float4*)(att + (size_t)n * T_);
    const int nv4 = (lens[n] + 3) >> 2;
    for (int i = tid; i < nv4; i += 256) {
        const float sc = s[i >> 5];               // i*4 / CHUNK
        float4 v = a4[i];
        v.x *= sc; v.y *= sc; v.z *= sc; v.w *= sc;
        a4[i] = v;
    }
}

extern "C" void kernel_launch(void* const* d_in, const int* in_sizes, int n_in,
                              void* d_out, int out_size)
{
    const float* q     = (const float*)d_in[0];
    const float* key   = (const float*)d_in[1];
    const float* value = (const float*)d_in[2];
    const int*   lens  = (const int*)  d_in[3];

    float* out = (float*)d_out;
    float* ctx = out;                 // (N, V)
    float* att = out + N_ * V_;       // (N, T)

    dim3 gA(SPLITS, N_);
    attn_partial<<<gA, 256>>>(q, key, value, lens, att);
    attn_combine<<<N_, 256>>>(ctx, att, lens);
}